// round 7
// baseline (speedup 1.0000x reference)
#include <cuda_runtime.h>
#include <math.h>

// ---------------- problem constants ----------------
#define T_LEN  2048
#define BSZ    16
#define NHEAD  8
#define DIM    64
#define BH     (BSZ*NHEAD)        // 128
#define NROWS  (BH*T_LEN)         // 262144
#define M_FEAT 266
#define M_PAD  272                // padded row (68 float4), tails are zero

#define DN        0.35355339059327373f   // 64^-0.25
#define HALF_DN2  0.0625f                // 0.5 * 64^-0.5
#define RATIO     0.06131398166796437f   // 266^-0.5
#define EPS_KER   1e-4f
#define EPS_DEN   1e-6f
#define QSCALE    0.125f                 // 64^-0.5

typedef unsigned long long u64;

// ---------------- scratch (__device__ globals; no allocs allowed) ----------------
__device__ float g_qh[(size_t)NROWS*DIM];
__device__ float g_kh[(size_t)NROWS*DIM];
__device__ float g_vh[(size_t)NROWS*DIM];
__device__ float g_qf[(size_t)NROWS*M_PAD];
__device__ float g_kf[(size_t)NROWS*M_PAD];   // raw dd for k (transformed in-scan)
__device__ float g_kdiag[(size_t)NROWS];
__device__ float g_temp[(size_t)NROWS*DIM];
__device__ unsigned g_kmax;
// transposed weights (coalesced mainloop loads)
__device__ float g_WT[3*64*512];      // [which][d][o]
__device__ float g_WoT[512*64];       // [o][e]
__device__ float g_projT[64*M_PAD];   // [d][m]

// ---------------- helpers ----------------
__device__ __forceinline__ unsigned fenc(float x){
    unsigned u = __float_as_uint(x);
    return (u & 0x80000000u) ? ~u : (u | 0x80000000u);
}
__device__ __forceinline__ float fdec(unsigned k){
    return (k & 0x80000000u) ? __uint_as_float(k ^ 0x80000000u)
                             : __uint_as_float(~k);
}
__device__ __forceinline__ void cp_async16(void* s, const void* g){
    unsigned sa = (unsigned)__cvta_generic_to_shared(s);
    asm volatile("cp.async.ca.shared.global [%0],[%1],16;\n" :: "r"(sa), "l"(g));
}
__device__ __forceinline__ void cp_async4(void* s, const void* g){
    unsigned sa = (unsigned)__cvta_generic_to_shared(s);
    asm volatile("cp.async.ca.shared.global [%0],[%1],4;\n" :: "r"(sa), "l"(g));
}
__device__ __forceinline__ void cp_commit(){ asm volatile("cp.async.commit_group;\n"); }
__device__ __forceinline__ void cp_wait0(){ asm volatile("cp.async.wait_group 0;\n"); }
__device__ __forceinline__ void cp_wait2(){ asm volatile("cp.async.wait_group 2;\n"); }
__device__ __forceinline__ void cp_wait4(){ asm volatile("cp.async.wait_group 4;\n"); }

// packed f32x2 (Blackwell): two independent fp32 FMAs per issue slot
__device__ __forceinline__ u64 fma2(u64 a, u64 b, u64 c){
    u64 d; asm("fma.rn.f32x2 %0, %1, %2, %3;" : "=l"(d) : "l"(a), "l"(b), "l"(c)); return d;
}
__device__ __forceinline__ u64 pack2(float lo, float hi){
    u64 d; asm("mov.b64 %0, {%1, %2};" : "=l"(d) : "f"(lo), "f"(hi)); return d;
}
__device__ __forceinline__ float2 unpack2(u64 v){
    float2 r; asm("mov.b64 {%0, %1}, %2;" : "=f"(r.x), "=f"(r.y) : "l"(v)); return r;
}

// ---------------- kernels ----------------
__global__ void k_init(){ if (threadIdx.x==0) g_kmax = 0u; }

// One-shot transposes: W[o][d] -> WT[d][o]; Wo[e][o] -> WoT[o][e]; proj[m][d] -> projT[d][m]
__global__ void k_transp(const float* __restrict__ Wq, const float* __restrict__ Wk,
                         const float* __restrict__ Wv, const float* __restrict__ Wo,
                         const float* __restrict__ proj){
    const int which = blockIdx.y;
    const int idx = blockIdx.x*256 + threadIdx.x;
    if (which < 3){
        const float* src = (which==0) ? Wq : (which==1) ? Wk : Wv;
        float* dst = g_WT + (size_t)which*64*512;
        if (idx < 512*64){ int o = idx >> 6, d = idx & 63; dst[d*512 + o] = __ldg(src + idx); }
    } else if (which == 3){
        if (idx < 64*512){ int e = idx >> 9, o = idx & 511; g_WoT[o*64 + e] = __ldg(Wo + idx); }
    } else {
        if (idx < M_FEAT*64){ int m = idx >> 6, d = idx & 63; g_projT[d*M_PAD + m] = __ldg(proj + idx); }
    }
}

// QKV head projections, tiled 16 rows (= one t, all b) per CTA. y selects (q,k,v).
__global__ void __launch_bounds__(256) k_proj(const float* __restrict__ q,
                       const float* __restrict__ k, const float* __restrict__ v,
                       const float* __restrict__ bq, const float* __restrict__ bk,
                       const float* __restrict__ bv){
    __shared__ __align__(16) float xs[64*18];   // [d][row], stride 18 (8B-aligned pairs)
    const int t = blockIdx.x;
    const int which = blockIdx.y;
    const float* x; const float* bias; float* out; float scale;
    if (which==0){ x=q; bias=bq; out=g_qh; scale=QSCALE; }
    else if (which==1){ x=k; bias=bk; out=g_kh; scale=1.f; }
    else { x=v; bias=bv; out=g_vh; scale=1.f; }
    const float* WT = g_WT + (size_t)which*64*512;
    const int tid = threadIdx.x;
    {
        int r = tid >> 4, dg = tid & 15;       // r = b (0..15)
        float4 vv = __ldg((const float4*)(x + ((size_t)t*16 + r)*64 + dg*4));
        xs[(dg*4+0)*18 + r] = vv.x;
        xs[(dg*4+1)*18 + r] = vv.y;
        xs[(dg*4+2)*18 + r] = vv.z;
        xs[(dg*4+3)*18 + r] = vv.w;
    }
    __syncthreads();
    const int o0 = tid, o1 = tid + 256;
    u64 a0[8], a1[8];
    #pragma unroll
    for (int i=0;i<8;i++){ a0[i]=0ull; a1[i]=0ull; }
    #pragma unroll 8
    for (int d=0; d<64; d++){
        float w0 = __ldg(WT + d*512 + o0);     // lanes: consecutive o -> coalesced
        float w1 = __ldg(WT + d*512 + o1);
        u64 pw0 = pack2(w0,w0), pw1 = pack2(w1,w1);
        const u64* xp = (const u64*)&xs[d*18];
        #pragma unroll
        for (int r2=0;r2<8;r2++){
            u64 xv = xp[r2];                   // broadcast within warp
            a0[r2] = fma2(pw0, xv, a0[r2]);
            a1[r2] = fma2(pw1, xv, a1[r2]);
        }
    }
    const float b0v = __ldg(bias + o0), b1v = __ldg(bias + o1);
    const int h0 = o0 >> 6, d0 = o0 & 63, h1 = o1 >> 6, d1 = o1 & 63;
    #pragma unroll
    for (int r2=0;r2<8;r2++){
        float2 v0 = unpack2(a0[r2]);
        float2 v1 = unpack2(a1[r2]);
        int b0 = 2*r2, b1 = 2*r2+1;
        out[(((size_t)(b0*NHEAD + h0))*T_LEN + t)*DIM + d0] = (v0.x + b0v)*scale;
        out[(((size_t)(b1*NHEAD + h0))*T_LEN + t)*DIM + d0] = (v0.y + b0v)*scale;
        out[(((size_t)(b0*NHEAD + h1))*T_LEN + t)*DIM + d1] = (v1.x + b1v)*scale;
        out[(((size_t)(b1*NHEAD + h1))*T_LEN + t)*DIM + d1] = (v1.y + b1v)*scale;
    }
}

// Feature maps, tiled 32 rows (same bh, consecutive t) per CTA, 288 threads (m = tid).
// blockIdx.y==0: q path (per-row max -> write qf, pads zeroed).
// blockIdx.y==1: k path (write raw dd + diag; CTA max -> global atomicMax).
__global__ void __launch_bounds__(288) k_feat(){
    __shared__ __align__(16) float xs[64*36];   // [d][row], stride 36 (8B-aligned pairs)
    __shared__ float sdd[32*272];               // [row][m]
    __shared__ float sdiag[32], smax[32];
    const int tid = threadIdx.x;
    const bool IS_Q = (blockIdx.y == 0);
    const size_t row0 = (size_t)blockIdx.x * 32;
    const float* src = (IS_Q ? g_qh : g_kh) + row0*64;
    if (tid < 256){
        #pragma unroll
        for (int half=0; half<2; half++){
            int i = tid + half*256;
            int r = i >> 4, dg = i & 15;
            float4 vv = __ldg((const float4*)(src + (size_t)r*64 + dg*4));
            xs[(dg*4+0)*36 + r] = vv.x;
            xs[(dg*4+1)*36 + r] = vv.y;
            xs[(dg*4+2)*36 + r] = vv.z;
            xs[(dg*4+3)*36 + r] = vv.w;
        }
    }
    __syncthreads();
    const int m = tid;
    float dd[32];
    if (m < M_FEAT){
        u64 acc[16];
        #pragma unroll
        for (int i=0;i<16;i++) acc[i]=0ull;
        #pragma unroll 4
        for (int d=0; d<64; d++){
            float p = __ldg(g_projT + d*M_PAD + m);   // coalesced; high L1 reuse
            u64 pw = pack2(p, p);
            const u64* xp = (const u64*)&xs[d*36];
            #pragma unroll
            for (int r2=0;r2<16;r2++) acc[r2] = fma2(pw, xp[r2], acc[r2]);
        }
        #pragma unroll
        for (int r2=0;r2<16;r2++){
            float2 v = unpack2(acc[r2]);
            dd[2*r2]   = v.x * DN;
            dd[2*r2+1] = v.y * DN;
            sdd[(2*r2)*272 + m]   = dd[2*r2];
            sdd[(2*r2+1)*272 + m] = dd[2*r2+1];
        }
    }
    __syncthreads();
    // warps 0..7: rows 4w..4w+3 -> row max + diag
    const int w = tid >> 5, lane = tid & 31;
    if (w < 8){
        #pragma unroll
        for (int rr=0; rr<4; rr++){
            const int r = 4*w + rr;
            float mx = -3.0e38f;
            #pragma unroll
            for (int c=0;c<8;c++) mx = fmaxf(mx, sdd[r*272 + lane + 32*c]);
            if (lane < 10) mx = fmaxf(mx, sdd[r*272 + 256 + lane]);
            #pragma unroll
            for (int o=16;o;o>>=1) mx = fmaxf(mx, __shfl_xor_sync(0xffffffffu, mx, o));
            float a = xs[lane*36 + r], b = xs[(lane+32)*36 + r];
            float s = a*a + b*b;
            #pragma unroll
            for (int o=16;o;o>>=1) s += __shfl_xor_sync(0xffffffffu, s, o);
            if (lane == 0){ smax[r] = mx; sdiag[r] = s * HALF_DN2; }
        }
    }
    __syncthreads();
    if (IS_Q){
        if (m < M_FEAT){
            float* dst = g_qf + row0*M_PAD + m;
            #pragma unroll
            for (int r=0;r<32;r++)
                dst[(size_t)r*M_PAD] = RATIO * (expf(dd[r] - sdiag[r] - smax[r]) + EPS_KER);
        } else if (m < M_PAD){
            float* dst = g_qf + row0*M_PAD + m;
            #pragma unroll
            for (int r=0;r<32;r++) dst[(size_t)r*M_PAD] = 0.f;
        }
    } else {
        if (m < M_FEAT){
            float* dst = g_kf + row0*M_PAD + m;
            #pragma unroll
            for (int r=0;r<32;r++) dst[(size_t)r*M_PAD] = dd[r];
        }
        if (w == 8) g_kdiag[row0 + lane] = sdiag[lane];   // lanes 0..31 = rows 0..31
        if (tid == 0){
            float mm = smax[0];
            #pragma unroll
            for (int i=1;i<32;i++) mm = fmaxf(mm, smax[i]);
            atomicMax(&g_kmax, fenc(mm));
        }
    }
}

// Causal linear-attention scan: one CTA per (b,h), S[272x64] packed f32x2 in regs.
// 8-buffer cp.async pipeline, 2 steps per iteration, fused k-feature transform
// (tiles 2i+2, 2i+3 transformed during iter i), one __syncthreads per iteration;
// outputs of iter i-1 written at iter i. z held in registers.
__global__ void __launch_bounds__(256,1) k_scan(){
    __shared__ __align__(16) float sk[8][M_PAD];
    __shared__ __align__(16) float sq[8][M_PAD];
    __shared__ __align__(16) float sv[8][64];
    __shared__ float skd[8];
    __shared__ float psumb[2][2][256];
    __shared__ float denp[2][2][8];
    const int tid = threadIdx.x;
    const int bh  = blockIdx.x;
    const float MX = fdec(g_kmax);
    float z1r = 0.f, z2r = 0.f;        // z[tid], z[256+tid] (tid<16)
    u64 S[34];
    #pragma unroll
    for (int i=0;i<34;i++) S[i] = 0ull;
    const float* kbase = g_kf + (size_t)bh*T_LEN*M_PAD;
    const float* qbase = g_qf + (size_t)bh*T_LEN*M_PAD;
    const float* vbase = g_vh + (size_t)bh*T_LEN*DIM;
    const float* dbase = g_kdiag + (size_t)bh*T_LEN;
    float*       obase = g_temp + (size_t)bh*T_LEN*DIM;
    const int NSTEP = T_LEN - 1;   // 2047
    const int NPAIR = NSTEP / 2;   // 1023 (steps 0..2045), epilogue: step 2046

    #define ISSUE(t, buf)                                                          \
        do {                                                                       \
            if (tid < 68)       cp_async16(&sk[buf][tid*4],      kbase + (size_t)(t)*M_PAD + tid*4);        \
            else if (tid < 136) cp_async16(&sq[buf][(tid-68)*4], qbase + (size_t)((t)+1)*M_PAD + (tid-68)*4);\
            else if (tid < 152) cp_async16(&sv[buf][(tid-136)*4],vbase + (size_t)(t)*DIM + (tid-136)*4);    \
            else if (tid == 152) cp_async4(&skd[buf], dbase + (t));                                          \
        } while(0)

    // in-place kf transform of tile 'tt' (raw dd -> RATIO*(exp(dd-kd-MX)+eps), pads->0)
    #define KTRANS(tt)                                                             \
        do {                                                                       \
            const int tb_ = (tt) & 7;                                              \
            const float kd_ = skd[tb_];                                            \
            float kv_ = sk[tb_][tid];                                              \
            sk[tb_][tid] = RATIO * (expf(kv_ - kd_ - MX) + EPS_KER);               \
            if (tid < 16){                                                         \
                if (tid < 10){                                                     \
                    float k2_ = sk[tb_][256+tid];                                  \
                    sk[tb_][256+tid] = RATIO * (expf(k2_ - kd_ - MX) + EPS_KER);   \
                } else sk[tb_][256+tid] = 0.f;                                     \
            }                                                                      \
        } while(0)

    // one scan step: tile 'bb', results -> psumb/denp[ph][ss]
    #define STEP(bb, ph, ss)                                                       \
        do {                                                                       \
            const ulonglong2* k2_ = (const ulonglong2*)&sk[bb][g*68];              \
            const ulonglong2* q2_ = (const ulonglong2*)&sq[bb][g*68];              \
            const float ve_ = sv[bb][e];                                           \
            const u64 vv_ = pack2(ve_, ve_);                                       \
            u64 pA_ = 0ull, pB_ = 0ull;                                            \
            _Pragma("unroll")                                                      \
            for (int j=0;j<17;j++){                                                \
                ulonglong2 kk_ = k2_[j], qq_ = q2_[j];                             \
                S[2*j]   = fma2(kk_.x, vv_, S[2*j]);   pA_ = fma2(qq_.x, S[2*j],   pA_); \
                S[2*j+1] = fma2(kk_.y, vv_, S[2*j+1]); pB_ = fma2(qq_.y, S[2*j+1], pB_); \
            }                                                                      \
            float2 a_ = unpack2(pA_), b_ = unpack2(pB_);                           \
            psumb[ph][ss][tid] = (a_.x + a_.y) + (b_.x + b_.y);                    \
            z1r += sk[bb][tid];                                                    \
            float dp_ = sq[bb][tid] * (z1r + EPS_DEN);                             \
            if (tid < 16){                                                         \
                z2r += sk[bb][256+tid];                                            \
                dp_ += sq[bb][256+tid] * (z2r + EPS_DEN);                          \
            }                                                                      \
            _Pragma("unroll")                                                      \
            for (int o_=16;o_;o_>>=1) dp_ += __shfl_down_sync(0xffffffffu, dp_, o_);\
            if ((tid & 31) == 0) denp[ph][ss][tid >> 5] = dp_;                     \
        } while(0)

    #define OUTW(ph, ss, row)                                                      \
        do {                                                                       \
            const float* ps_ = psumb[ph][ss];                                      \
            const float* dn_ = denp[ph][ss];                                       \
            float num_ = ps_[e] + ps_[64+e] + ps_[128+e] + ps_[192+e];             \
            float den_ = dn_[0]+dn_[1]+dn_[2]+dn_[3]+dn_[4]+dn_[5]+dn_[6]+dn_[7];  \
            obase[(size_t)(row)*DIM + e] = num_ / den_;                            \
        } while(0)

    // preload tiles 0..5 (one commit group per tile)
    ISSUE(0,0); cp_commit();
    ISSUE(1,1); cp_commit();
    ISSUE(2,2); cp_commit();
    ISSUE(3,3); cp_commit();
    ISSUE(4,4); cp_commit();
    ISSUE(5,5); cp_commit();
    cp_wait4();                 // tiles 0,1 complete
    __syncthreads();
    KTRANS(0); KTRANS(1);

    const int g = tid >> 6, e = tid & 63;
    for (int i = 0; i < NPAIR; i++){
        const int t0 = 2*i;
        const int b0 = t0 & 7, b1 = (t0+1) & 7;
        const int cur = i & 1;
        cp_wait2();               // committed 6+2i groups; complete -> tiles <= t0+3
        __syncthreads();          // tiles + transforms + iter i-1 psum/denp visible;
                                  // reads of buffers (t0+6)&7,(t0+7)&7 (iter i-1) done

        if (i > 0 && tid < 64){   // deferred: steps t0-2 -> row t0-1, t0-1 -> row t0
            OUTW(cur^1, 0, t0-1);
            OUTW(cur^1, 1, t0);
        }

        if (t0+6 < NSTEP) ISSUE(t0+6, (t0+6)&7);
        cp_commit();
        if (t0+7 < NSTEP) ISSUE(t0+7, (t0+7)&7);
        cp_commit();

        KTRANS(t0+2);                         // t0+2 <= 2046 always in loop
        if (t0+3 < NSTEP) KTRANS(t0+3);

        STEP(b0, cur, 0);
        STEP(b1, cur, 1);
    }

    // epilogue: write steps 2044,2045; then step 2046 -> row 2047
    cp_wait0();
    __syncthreads();
    if (tid < 64){
        const int lcur = (NPAIR-1) & 1;       // cur of last iteration (i=1022 -> 0)
        OUTW(lcur, 0, NSTEP-2);               // step 2044 -> row 2045
        OUTW(lcur, 1, NSTEP-1);               // step 2045 -> row 2046
    }
    {
        const int bb = (NSTEP-1) & 7;         // tile 2046 (transformed at iter 1022)
        STEP(bb, 1, 0);
    }
    __syncthreads();
    if (tid < 64) OUTW(1, 0, NSTEP);          // step 2046 -> row 2047

    #undef ISSUE
    #undef KTRANS
    #undef STEP
    #undef OUTW
}

// Output projection, tiled: one CTA per t (16 b-rows). out[t,b,e]; t=0 -> bo.
__global__ void __launch_bounds__(256) k_out(const float* __restrict__ bo,
                                             float* __restrict__ out){
    __shared__ __align__(16) float ms[512*18];   // [o][b], stride 18; reused as psq
    const int t = blockIdx.x;
    const int tid = threadIdx.x;
    if (t == 0){
        for (int i = tid; i < 1024; i += 256){
            int b = i >> 6, e = i & 63;
            out[(size_t)b*64 + e] = __ldg(bo + e);
        }
        return;
    }
    for (int i = tid; i < 2048; i += 256){
        int b = i >> 7, rem = i & 127, h = rem >> 4, dg = rem & 15;
        float4 v = __ldg((const float4*)(g_temp + (((size_t)(b*NHEAD + h))*T_LEN + t)*DIM + dg*4));
        int o = h*64 + dg*4;
        ms[(o+0)*18 + b] = v.x;
        ms[(o+1)*18 + b] = v.y;
        ms[(o+2)*18 + b] = v.z;
        ms[(o+3)*18 + b] = v.w;
    }
    __syncthreads();
    const int e = tid & 63, q = tid >> 6;
    u64 acc[8];
    #pragma unroll
    for (int i=0;i<8;i++) acc[i]=0ull;
    #pragma unroll 4
    for (int j=0;j<128;j++){
        const int o = q*128 + j;
        float wv = __ldg(g_WoT + o*64 + e);          // lanes: consecutive e -> coalesced
        u64 pw = pack2(wv, wv);
        const u64* mp = (const u64*)&ms[o*18];
        #pragma unroll
        for (int r2=0;r2<8;r2++) acc[r2] = fma2(pw, mp[r2], acc[r2]);
    }
    __syncthreads();                 // all ms reads done before reuse
    float* psq = ms;                 // [q*64+e][17] partials
    #pragma unroll
    for (int r2=0;r2<8;r2++){
        float2 v = unpack2(acc[r2]);
        psq[(q*64 + e)*17 + 2*r2]     = v.x;
        psq[(q*64 + e)*17 + 2*r2 + 1] = v.y;
    }
    __syncthreads();
    for (int i = tid; i < 1024; i += 256){
        int b = i >> 6, e2 = i & 63;
        float num = psq[(e2)*17 + b] + psq[(64+e2)*17 + b]
                  + psq[(128+e2)*17 + b] + psq[(192+e2)*17 + b];
        out[((size_t)t*16 + b)*64 + e2] = num + __ldg(bo + e2);
    }
}

// ---------------- launch ----------------
extern "C" void kernel_launch(void* const* d_in, const int* in_sizes, int n_in,
                              void* d_out, int out_size){
    const float* query = (const float*)d_in[0];
    const float* key_  = (const float*)d_in[1];
    const float* value = (const float*)d_in[2];
    const float* Wq    = (const float*)d_in[3];
    const float* bq    = (const float*)d_in[4];
    const float* Wk    = (const float*)d_in[5];
    const float* bk    = (const float*)d_in[6];
    const float* Wv    = (const float*)d_in[7];
    const float* bv    = (const float*)d_in[8];
    const float* Wo    = (const float*)d_in[9];
    const float* bo    = (const float*)d_in[10];
    const float* proj  = (const float*)d_in[11];
    float* out = (float*)d_out;

    k_init<<<1, 32>>>();
    k_transp<<<dim3(128, 5), 256>>>(Wq, Wk, Wv, Wo, proj);
    k_proj<<<dim3(T_LEN, 3), 256>>>(query, key_, value, bq, bk, bv);
    k_feat<<<dim3(NROWS/32, 2), 288>>>();
    k_scan<<<BH, 256>>>();
    k_out<<<T_LEN, 256>>>(bo, out);
}